// round 4
// baseline (speedup 1.0000x reference)
#include <cuda_runtime.h>

#define B_   8
#define C_   64
#define H_   128
#define W_   128
#define O_   16      // C / RED
#define G_   32      // groups
#define GC_  2       // channels per group
#define KK_  9       // 3x3

typedef unsigned long long u64;

__device__ __forceinline__ u64 pack2(float lo, float hi) {
    u64 r;
    asm("mov.b64 %0, {%1,%2};" : "=l"(r) : "f"(lo), "f"(hi));
    return r;
}
__device__ __forceinline__ void unpack2(u64 v, float& lo, float& hi) {
    asm("mov.b64 {%0,%1}, %2;" : "=f"(lo), "=f"(hi) : "l"(v));
}
// d = a*b + d, packed f32x2 (Blackwell FFMA2)
__device__ __forceinline__ void fma2(u64& d, u64 a, u64 b) {
    asm("fma.rn.f32x2 %0, %1, %2, %0;" : "+l"(d) : "l"(a), "l"(b));
}

__global__ void __launch_bounds__(128, 4) involution_fused_kernel(
    const float* __restrict__ x,
    const float* __restrict__ w1,
    const float* __restrict__ b1,
    const float* __restrict__ pa,
    const float* __restrict__ w2,
    const float* __restrict__ b2,
    float* __restrict__ out)
{
    // Duplicated-scalar (s,s) weight tables so FFMA2 multiplicand is one LDS.64
    __shared__ float2 s_w1[C_ * O_];        // [c][o]   : 8 KB
    __shared__ float2 s_w2[G_ * O_ * KK_];  // [g][o][kk]: 36 KB
    __shared__ float2 s_b2[G_ * KK_];       // [g][kk]  : 2.25 KB

    const int tid = threadIdx.y * 64 + threadIdx.x;

    for (int i = tid; i < C_ * O_; i += 128) {
        int c = i >> 4, o = i & 15;
        float v = w1[o * C_ + c];
        s_w1[i] = make_float2(v, v);
    }
    for (int i = tid; i < G_ * O_ * KK_; i += 128) {
        int kk = i % KK_;
        int rest = i / KK_;
        int o = rest & 15;
        int g = rest >> 4;
        float v = w2[(g * KK_ + kk) * O_ + o];
        s_w2[i] = make_float2(v, v);
    }
    for (int i = tid; i < G_ * KK_; i += 128) {
        float v = b2[i];
        s_b2[i] = make_float2(v, v);
    }
    __syncthreads();

    const int b = blockIdx.z;
    const int h = blockIdx.y * 2 + threadIdx.y;
    const int w = threadIdx.x * 2;          // pixel pair (w, w+1)
    const float alpha = pa[0];

    const float* xb = x + (size_t)b * C_ * H_ * W_;
    const float* xc = xb + h * W_ + w;

    // ---- Phase 1: t = w1 @ x_center + b1 (packed over the 2 pixels) ----
    u64 t2[O_];
#pragma unroll
    for (int o = 0; o < O_; o++) {
        float bv = b1[o];
        t2[o] = pack2(bv, bv);
    }

#pragma unroll 4
    for (int c = 0; c < C_; c++) {
        float2 xv = *reinterpret_cast<const float2*>(xc + c * (H_ * W_));
        u64 xp = pack2(xv.x, xv.y);
        const ulonglong2* wv = reinterpret_cast<const ulonglong2*>(&s_w1[c * O_]);
#pragma unroll
        for (int o2 = 0; o2 < 8; o2++) {
            ulonglong2 wpair = wv[o2];   // LDS.128: two duplicated scalars
            fma2(t2[2 * o2 + 0], xp, wpair.x);
            fma2(t2[2 * o2 + 1], xp, wpair.y);
        }
    }

    // ---- PReLU (single shared slope) ----
#pragma unroll
    for (int o = 0; o < O_; o++) {
        float a, bb;
        unpack2(t2[o], a, bb);
        a  = (a  >= 0.f) ? a  : alpha * a;
        bb = (bb >= 0.f) ? bb : alpha * bb;
        t2[o] = pack2(a, bb);
    }

    const bool hv0 = (h > 0);
    const bool hv2 = (h < H_ - 1);
    const bool wv0 = (w > 0);
    const bool wv2 = (w + 2 < W_);

    float* outp = out + (size_t)b * C_ * H_ * W_ + h * W_ + w;
    const u64* s_b2u = reinterpret_cast<const u64*>(s_b2);

    // ---- Phase 2+3 per group: 9 per-pixel weights, then 3x3 gather ----
#pragma unroll 1
    for (int g = 0; g < G_; g++) {
        u64 wk[KK_];
#pragma unroll
        for (int kk = 0; kk < KK_; kk++) wk[kk] = s_b2u[g * KK_ + kk];

#pragma unroll
        for (int o = 0; o < O_; o++) {
            u64 tv = t2[o];
            const u64* wrow = reinterpret_cast<const u64*>(&s_w2[(g * O_ + o) * KK_]);
#pragma unroll
            for (int kk = 0; kk < KK_; kk++) fma2(wk[kk], tv, wrow[kk]);
        }

#pragma unroll
        for (int cc = 0; cc < GC_; cc++) {
            const int c = g * GC_ + cc;
            const float* xr = xb + (size_t)c * (H_ * W_) + h * W_ + w;
            u64 acc = 0ULL;  // (0.f, 0.f)
#pragma unroll
            for (int di = 0; di < 3; di++) {
                const bool hv = (di == 0) ? hv0 : ((di == 2) ? hv2 : true);
                const float* row = xr + (di - 1) * W_;
                float  L = (hv && wv0) ? row[-1] : 0.f;
                float2 m = hv ? *reinterpret_cast<const float2*>(row)
                              : make_float2(0.f, 0.f);
                float  R = (hv && wv2) ? row[2] : 0.f;
                fma2(acc, wk[3 * di + 0], pack2(L,   m.x));
                fma2(acc, wk[3 * di + 1], pack2(m.x, m.y));
                fma2(acc, wk[3 * di + 2], pack2(m.y, R));
            }
            float a0, a1;
            unpack2(acc, a0, a1);
            *reinterpret_cast<float2*>(outp + (size_t)c * (H_ * W_)) =
                make_float2(a0, a1);
        }
    }
}

extern "C" void kernel_launch(void* const* d_in, const int* in_sizes, int n_in,
                              void* d_out, int out_size)
{
    (void)in_sizes; (void)n_in; (void)out_size;
    const float* x  = (const float*)d_in[0];
    const float* w1 = (const float*)d_in[1];
    const float* b1 = (const float*)d_in[2];
    const float* pa = (const float*)d_in[3];
    const float* w2 = (const float*)d_in[4];
    const float* b2 = (const float*)d_in[5];
    float* out = (float*)d_out;

    dim3 block(64, 2, 1);            // 128 threads = 64 pixel-pairs x 2 rows
    dim3 grid(1, H_ / 2, B_);        // 512 CTAs
    involution_fused_kernel<<<grid, block>>>(x, w1, b1, pa, w2, b2, out);
}

// round 7
// speedup vs baseline: 1.0216x; 1.0216x over previous
#include <cuda_runtime.h>

#define B_   8
#define C_   64
#define H_   128
#define W_   128
#define O_   16      // C / RED
#define G_   32      // total groups
#define GH_  16      // groups per CTA (group-half)
#define GC_  2       // channels per group
#define KK_  9       // 3x3
#define KP_  10      // padded kernel stride (u64 units) for 16B alignment

typedef unsigned long long u64;

__device__ __forceinline__ u64 pack2(float lo, float hi) {
    u64 r;
    asm("mov.b64 %0, {%1,%2};" : "=l"(r) : "f"(lo), "f"(hi));
    return r;
}
__device__ __forceinline__ void unpack2(u64 v, float& lo, float& hi) {
    asm("mov.b64 {%0,%1}, %2;" : "=f"(lo), "=f"(hi) : "l"(v));
}
// d = a*b + d, packed f32x2 (Blackwell FFMA2)
__device__ __forceinline__ void fma2(u64& d, u64 a, u64 b) {
    asm("fma.rn.f32x2 %0, %1, %2, %0;" : "+l"(d) : "l"(a), "l"(b));
}

__global__ void __launch_bounds__(128, 5) involution_fused_kernel(
    const float* __restrict__ x,
    const float* __restrict__ w1,
    const float* __restrict__ b1,
    const float* __restrict__ pa,
    const float* __restrict__ w2,
    const float* __restrict__ b2,
    float* __restrict__ out)
{
    // Duplicated-scalar (s,s) weight tables so FFMA2 multiplicand is one LDS
    __shared__ float2 s_w1[C_ * O_];         // [c][o]            : 8 KB
    __shared__ float2 s_w2[GH_ * O_ * KP_];  // [gl][o][kk pad10] : 20 KB
    __shared__ float2 s_b2[GH_ * KP_];       // [gl][kk pad10]    : 1.25 KB

    const int tid = threadIdx.y * 64 + threadIdx.x;
    const int g0  = blockIdx.x * GH_;        // group-half base

    for (int i = tid; i < C_ * O_; i += 128) {
        int c = i >> 4, o = i & 15;
        float v = w1[o * C_ + c];
        s_w1[i] = make_float2(v, v);
    }
    // half of w2, padded row stride KP_
    for (int i = tid; i < GH_ * O_ * KK_; i += 128) {
        int kk = i % KK_;
        int rest = i / KK_;
        int o  = rest & 15;
        int gl = rest >> 4;
        float v = w2[((g0 + gl) * KK_ + kk) * O_ + o];
        s_w2[(gl * O_ + o) * KP_ + kk] = make_float2(v, v);
    }
    // BUGFIX (R6): GH_*KP_ = 160 > blockDim 128 — must stride, not mask
    for (int i = tid; i < GH_ * KP_; i += 128) {
        int gl = i / KP_, kk = i % KP_;
        float v = (kk < KK_) ? b2[(g0 + gl) * KK_ + kk] : 0.f;
        s_b2[i] = make_float2(v, v);
    }
    __syncthreads();

    const int b = blockIdx.z;
    const int h = blockIdx.y * 2 + threadIdx.y;
    const int w = threadIdx.x * 2;          // pixel pair (w, w+1)
    const float alpha = pa[0];

    const float* xb = x + (size_t)b * C_ * H_ * W_;
    const float* xc = xb + h * W_ + w;

    // ---- Phase 1: t = w1 @ x_center + b1 (packed over the 2 pixels) ----
    u64 t2[O_];
#pragma unroll
    for (int o = 0; o < O_; o++) {
        float bv = b1[o];
        t2[o] = pack2(bv, bv);
    }

#pragma unroll 4
    for (int c = 0; c < C_; c++) {
        float2 xv = *reinterpret_cast<const float2*>(xc + c * (H_ * W_));
        u64 xp = pack2(xv.x, xv.y);
        const ulonglong2* wv = reinterpret_cast<const ulonglong2*>(&s_w1[c * O_]);
#pragma unroll
        for (int o2 = 0; o2 < 8; o2++) {
            ulonglong2 wpair = wv[o2];   // LDS.128: two duplicated scalars
            fma2(t2[2 * o2 + 0], xp, wpair.x);
            fma2(t2[2 * o2 + 1], xp, wpair.y);
        }
    }

    // ---- PReLU (single shared slope) ----
#pragma unroll
    for (int o = 0; o < O_; o++) {
        float a, bb;
        unpack2(t2[o], a, bb);
        a  = (a  >= 0.f) ? a  : alpha * a;
        bb = (bb >= 0.f) ? bb : alpha * bb;
        t2[o] = pack2(a, bb);
    }

    const bool hv0 = (h > 0);
    const bool hv2 = (h < H_ - 1);
    const bool wv0 = (w > 0);
    const bool wv2 = (w + 2 < W_);

    float* outp = out + (size_t)b * C_ * H_ * W_ + h * W_ + w;
    const u64* s_b2u = reinterpret_cast<const u64*>(s_b2);

    // ---- Phase 2+3 per group: 9 per-pixel weights, then 3x3 gather ----
#pragma unroll 1
    for (int gl = 0; gl < GH_; gl++) {
        u64 wk[KK_];
#pragma unroll
        for (int kk = 0; kk < KK_; kk++) wk[kk] = s_b2u[gl * KP_ + kk];

#pragma unroll
        for (int o = 0; o < O_; o++) {
            u64 tv = t2[o];
            const u64* wrow =
                reinterpret_cast<const u64*>(&s_w2[(gl * O_ + o) * KP_]);
#pragma unroll
            for (int kk = 0; kk < KK_; kk++) fma2(wk[kk], tv, wrow[kk]);
        }

#pragma unroll
        for (int cc = 0; cc < GC_; cc++) {
            const int c = (g0 + gl) * GC_ + cc;
            const float* xr = xb + (size_t)c * (H_ * W_) + h * W_ + w;
            u64 acc = 0ULL;  // (0.f, 0.f)
#pragma unroll
            for (int di = 0; di < 3; di++) {
                const bool hv = (di == 0) ? hv0 : ((di == 2) ? hv2 : true);
                const float* row = xr + (di - 1) * W_;
                float  L = (hv && wv0) ? row[-1] : 0.f;
                float2 m = hv ? *reinterpret_cast<const float2*>(row)
                              : make_float2(0.f, 0.f);
                float  R = (hv && wv2) ? row[2] : 0.f;
                fma2(acc, wk[3 * di + 0], pack2(L,   m.x));
                fma2(acc, wk[3 * di + 1], pack2(m.x, m.y));
                fma2(acc, wk[3 * di + 2], pack2(m.y, R));
            }
            float a0, a1;
            unpack2(acc, a0, a1);
            *reinterpret_cast<float2*>(outp + (size_t)c * (H_ * W_)) =
                make_float2(a0, a1);
        }
    }
}

extern "C" void kernel_launch(void* const* d_in, const int* in_sizes, int n_in,
                              void* d_out, int out_size)
{
    (void)in_sizes; (void)n_in; (void)out_size;
    const float* x  = (const float*)d_in[0];
    const float* w1 = (const float*)d_in[1];
    const float* b1 = (const float*)d_in[2];
    const float* pa = (const float*)d_in[3];
    const float* w2 = (const float*)d_in[4];
    const float* b2 = (const float*)d_in[5];
    float* out = (float*)d_out;

    dim3 block(64, 2, 1);            // 128 threads = 64 pixel-pairs x 2 rows
    dim3 grid(2, H_ / 2, B_);        // 1024 CTAs: x = group-half
    involution_fused_kernel<<<grid, block>>>(x, w1, b1, pa, w2, b2, out);
}